// round 8
// baseline (speedup 1.0000x reference)
#include <cuda_runtime.h>
#include <cuda_bf16.h>
#include <math.h>
#include <complex>
#include <algorithm>

// ============================================================================
// Problem constants (compile-time)
// ============================================================================
// irreps: 16 x (0e + 1o + 2e), FEAT = 144
// PATHS (l1,l2,l3) x 11, weights w_* : [11,16,16,16], w_dot : [3,16,16]

constexpr int T_L1[11] = {0,1,2,0,1,1,2,0,1,2,2};
constexpr int T_L2[11] = {0,1,2,1,0,2,1,2,1,0,2};
constexpr int T_L3[11] = {0,0,0,1,1,1,1,2,2,2,2};
// offsets into flat C array (sizes K1*K2*K3 per path)
constexpr int T_CO[11] = {0,1,10,35,44,53,98,143,168,213,238};
constexpr int C_TOTAL  = 363;
constexpr int T_IOFF[3] = {0,16,64};   // float offset of l-block within 144

struct Consts {
    float C[C_TOTAL];   // real Wigner-3j per path, unit Frobenius norm
    float scale[11];    // sqrt((2l3+1)/(n_paths[l3]*256))
    float dotmul;       // sqrt(1/768)/12
};

// ============================================================================
// Shared memory layout (in floats)
// ============================================================================
#define SM_W    0                 // 3 x 4096 staged W for current path
#define SM_C    12288             // 363 (+pad)
#define SM_WD   12656             // 768  w_dot
#define SM_X    13424             // 16 x 144
#define SM_OUT  15728             // 16 x 3 x 144 (q,k,v accumulators)
#define SM_B    22640             // 16 x B_STRIDE
#define B_STRIDE 1296             // >= 1280, ==16 (mod 32) for bank complement
#define SM_TOTAL (SM_B + 16*B_STRIDE)          // 43376 floats
#define SMEM_BYTES (SM_TOTAL * 4)              // 173504 bytes

// ============================================================================
// Per-path device body
// ============================================================================
template<int P>
__device__ __forceinline__ void run_path(float* __restrict__ sm, int wid, int lane, float scale)
{
    constexpr int L1 = T_L1[P], L2 = T_L2[P], L3 = T_L3[P];
    constexpr int K1 = 2*L1+1, K2 = 2*L2+1, K3 = 2*L3+1;
    constexpr int O1 = T_IOFF[L1], O2 = T_IOFF[L2], O3 = T_IOFF[L3];
    constexpr int CO = T_CO[P];

    const int nd = lane >> 4;        // which of the warp's 2 nodes
    const int v  = lane & 15;        // this lane's v index
    const int nl = wid*2 + nd;       // node slot 0..15
    const float* xn = sm + SM_X + nl*144;
    float*       bn = sm + SM_B + nl*B_STRIDE;
    const float* Csm = sm + SM_C + CO;

    // ---- Step A+B: areg[i,k] = sum_j x2[v,j] C[i,j,k]  (registers, lane-local)
    //      then b[u,v,k] = sum_i x1[u,i] areg[i,k]
    {
        float areg[K1*K3];
        {
            float xr[K2];
            #pragma unroll
            for (int j = 0; j < K2; j++) xr[j] = xn[O2 + v*K2 + j];
            #pragma unroll
            for (int i = 0; i < K1; i++)
                #pragma unroll
                for (int k = 0; k < K3; k++) {
                    float s = 0.f;
                    #pragma unroll
                    for (int j = 0; j < K2; j++)
                        s = fmaf(xr[j], Csm[(i*K2 + j)*K3 + k], s);
                    areg[i*K3 + k] = s;
                }
        }
        #pragma unroll 4
        for (int u = 0; u < 16; u++) {
            float xr[K1];
            #pragma unroll
            for (int i = 0; i < K1; i++) xr[i] = xn[O1 + u*K1 + i];
            #pragma unroll
            for (int k = 0; k < K3; k++) {
                float s = 0.f;
                #pragma unroll
                for (int i = 0; i < K1; i++)
                    s = fmaf(xr[i], areg[i*K3 + k], s);
                bn[(u*16 + v)*K3 + k] = s;
            }
        }
    }
    __syncwarp();

    // ---- Step C (heavy): out_t[w,k] += scale * sum_uv b[uv,k] W_t[uv,w]
    // lane -> (h = uv parity, wo = output w). acc over both nodes, 3 tensors.
    {
        const int h  = lane & 1;
        const int wo = lane >> 1;
        const float* b0 = sm + SM_B + (wid*2+0)*B_STRIDE + h*K3;
        const float* b1 = sm + SM_B + (wid*2+1)*B_STRIDE + h*K3;
        const float* wp = sm + SM_W + h*16 + wo;

        float acc0[3][K3], acc1[3][K3];
        #pragma unroll
        for (int t = 0; t < 3; t++)
            #pragma unroll
            for (int k = 0; k < K3; k++) { acc0[t][k] = 0.f; acc1[t][k] = 0.f; }

        #pragma unroll 4
        for (int s = 0; s < 128; s++) {
            float bv0[K3], bv1[K3];
            #pragma unroll
            for (int k = 0; k < K3; k++) { bv0[k] = b0[k]; bv1[k] = b1[k]; }
            #pragma unroll
            for (int t = 0; t < 3; t++) {
                float wv_ = wp[t*4096];
                #pragma unroll
                for (int k = 0; k < K3; k++) {
                    acc0[t][k] = fmaf(wv_, bv0[k], acc0[t][k]);
                    acc1[t][k] = fmaf(wv_, bv1[k], acc1[t][k]);
                }
            }
            b0 += 2*K3; b1 += 2*K3; wp += 32;
        }

        // pair-reduce across uv parity; lane h writes node h's outputs
        float* od = sm + SM_OUT + (wid*2 + h)*432 + O3 + wo*K3;
        #pragma unroll
        for (int t = 0; t < 3; t++)
            #pragma unroll
            for (int k = 0; k < K3; k++) {
                float send = h ? acc0[t][k] : acc1[t][k];   // my partial of partner's node
                float recv = __shfl_xor_sync(0xffffffffu, send, 1);
                float mine = h ? acc1[t][k] : acc0[t][k];   // my partial of my node
                od[t*144 + k] += scale * (mine + recv);
            }
    }
    __syncwarp();
}

// dot-product contribution for one l-block (half-warp per node, lane = u)
template<int L, int CO_, int DP>
__device__ __forceinline__ float dot_part(const float* __restrict__ sm,
                                          const float* __restrict__ qv,
                                          const float* __restrict__ kv, int u)
{
    constexpr int K = 2*L+1, OFF = T_IOFF[L];
    const float* Csm = sm + SM_C + CO_;
    const float* wd  = sm + SM_WD + DP*256 + u*16;
    float qm[K];
    #pragma unroll
    for (int m = 0; m < K; m++) qm[m] = qv[OFF + u*K + m];
    float qc[K];
    #pragma unroll
    for (int m2 = 0; m2 < K; m2++) {
        float s = 0.f;
        #pragma unroll
        for (int m = 0; m < K; m++) s = fmaf(qm[m], Csm[m*K + m2], s);
        qc[m2] = s;
    }
    float acc = 0.f;
    #pragma unroll
    for (int vv = 0; vv < 16; vv++) {
        float t = 0.f;
        #pragma unroll
        for (int m2 = 0; m2 < K; m2++) t = fmaf(qc[m2], kv[OFF + vv*K + m2], t);
        acc = fmaf(t, wd[vv], acc);
    }
    return acc;
}

// ============================================================================
// Kernel: 256 threads, 16 nodes/CTA (warp = 2 nodes)
// ============================================================================
__global__ void __launch_bounds__(256, 1)
tfn_kernel(const float* __restrict__ x,
           const float* __restrict__ wq, const float* __restrict__ wk,
           const float* __restrict__ wv, const float* __restrict__ wdot,
           float* __restrict__ out, int N, Consts cc)
{
    extern __shared__ float sm[];
    const int tid  = threadIdx.x;
    const int lane = tid & 31;
    const int wid  = tid >> 5;
    const int base = blockIdx.x * 16;

    // ---- stage constants, x tile, zero accumulators
    for (int i = tid; i < C_TOTAL; i += 256) sm[SM_C + i] = cc.C[i];
    for (int i = tid; i < 768; i += 256)     sm[SM_WD + i] = wdot[i];
    {
        const float4* xg = reinterpret_cast<const float4*>(x);
        float4* xs = reinterpret_cast<float4*>(sm + SM_X);
        const size_t lim = (size_t)N * 36;           // N*144/4
        for (int i = tid; i < 576; i += 256) {
            size_t g = (size_t)base * 36 + i;
            xs[i] = (g < lim) ? xg[g] : make_float4(0.f, 0.f, 0.f, 0.f);
        }
    }
    for (int i = tid; i < 6912; i += 256) sm[SM_OUT + i] = 0.f;
    __syncthreads();

#define DO_PATH(P)                                                                              \
    {                                                                                           \
        const float4* sq = reinterpret_cast<const float4*>(wq + (P)*4096);                      \
        const float4* sk = reinterpret_cast<const float4*>(wk + (P)*4096);                      \
        const float4* sv = reinterpret_cast<const float4*>(wv + (P)*4096);                      \
        float4* dW = reinterpret_cast<float4*>(sm + SM_W);                                      \
        for (int i = tid; i < 1024; i += 256) {                                                 \
            dW[i]        = sq[i];                                                               \
            dW[i + 1024] = sk[i];                                                               \
            dW[i + 2048] = sv[i];                                                               \
        }                                                                                       \
        __syncthreads();                                                                        \
        run_path<P>(sm, wid, lane, cc.scale[P]);                                                \
        __syncthreads();                                                                        \
    }

    DO_PATH(0)  DO_PATH(1)  DO_PATH(2)  DO_PATH(3)  DO_PATH(4)
    DO_PATH(5)  DO_PATH(6)  DO_PATH(7)  DO_PATH(8)  DO_PATH(9)  DO_PATH(10)
#undef DO_PATH

    // ---- epilogue: dot(q,k), attn, elu(attn*v) -> gmem
    {
        const int nd = lane >> 4;
        const int u  = lane & 15;
        const int nl = wid*2 + nd;
        const float* qv = sm + SM_OUT + nl*432;
        const float* kv = qv + 144;
        const float* vv = qv + 288;

        float acc = dot_part<0, 0, 0>(sm, qv, kv, u)
                  + dot_part<1, 1, 1>(sm, qv, kv, u)
                  + dot_part<2,10, 2>(sm, qv, kv, u);
        // reduce within the 16-lane half-warp
        acc += __shfl_xor_sync(0xffffffffu, acc, 1);
        acc += __shfl_xor_sync(0xffffffffu, acc, 2);
        acc += __shfl_xor_sync(0xffffffffu, acc, 4);
        acc += __shfl_xor_sync(0xffffffffu, acc, 8);

        float e    = expf(acc * cc.dotmul);
        float attn = e / (e + 1e-10f);

        const int ng = base + nl;
        if (ng < N) {
            float* og = out + (size_t)ng * 144;
            #pragma unroll
            for (int t = u; t < 144; t += 16) {
                float val = attn * vv[t];
                og[t] = (val > 0.f) ? val : expm1f(val);
            }
        }
    }
}

// ============================================================================
// Host: exact e3nn real Wigner-3j construction (same algorithm as reference)
// ============================================================================
static double factd(int n) { double r = 1.0; for (int i = 2; i <= n; i++) r *= i; return r; }

static double su2_cg(int j1, int m1, int j2, int m2, int j3, int m3)
{
    if (m3 != m1 + m2) return 0.0;
    int vmin = std::max(std::max(-j1 + j2 + m3, -j1 + m1), 0);
    int vmax = std::min(std::min(j2 + j3 + m1, j3 - j1 + j2), j3 + m3);
    double C = std::sqrt((2.0*j3 + 1.0) * factd(j3 + j1 - j2) * factd(j3 - j1 + j2)
                         * factd(j1 + j2 - j3) * factd(j3 + m3) * factd(j3 - m3)
                         / (factd(j1 + j2 + j3 + 1) * factd(j1 - m1) * factd(j1 + m1)
                            * factd(j2 - m2) * factd(j2 + m2)));
    double S = 0.0;
    for (int v = vmin; v <= vmax; v++) {
        double sgn = ((v + j2 + m2) & 1) ? -1.0 : 1.0;
        S += sgn * factd(j2 + j3 + m1 - v) * factd(j1 - m1 + v)
             / (factd(v) * factd(j3 - j1 + j2 - v) * factd(j3 + m3 - v)
                * factd(v + j1 - j2 - m3));
    }
    return C * S;
}

static void qmat(int l, std::complex<double> q[5][5])
{
    for (int i = 0; i < 5; i++) for (int j = 0; j < 5; j++) q[i][j] = 0.0;
    const double is2 = 1.0 / std::sqrt(2.0);
    for (int m = -l; m < 0; m++) {
        q[l + m][l - m] = is2;                              // l+|m|
        q[l + m][l + m] = std::complex<double>(0.0, -is2);  // l-|m|
    }
    q[l][l] = 1.0;
    for (int m = 1; m <= l; m++) {
        double sg = (m & 1) ? -1.0 : 1.0;
        q[l + m][l + m] = sg * is2;
        q[l + m][l - m] = std::complex<double>(0.0, sg * is2);
    }
    std::complex<double> ph(1.0, 0.0);
    for (int t = 0; t < l; t++) ph *= std::complex<double>(0.0, -1.0);  // (-1j)^l
    for (int i = 0; i < 2*l + 1; i++)
        for (int j = 0; j < 2*l + 1; j++) q[i][j] *= ph;
}

static void real_w3j(int l1, int l2, int l3, float* outv)
{
    const int K1 = 2*l1 + 1, K2 = 2*l2 + 1, K3 = 2*l3 + 1;
    std::complex<double> Q1[5][5], Q2[5][5], Q3[5][5];
    qmat(l1, Q1); qmat(l2, Q2); qmat(l3, Q3);

    double cg[5][5][5];
    for (int i = 0; i < K1; i++)
        for (int k = 0; k < K2; k++)
            for (int n = 0; n < K3; n++)
                cg[i][k][n] = su2_cg(l1, i - l1, l2, k - l2, l3, n - l3);

    double tmp[125]; double nrm = 0.0;
    for (int a = 0; a < K1; a++)
        for (int b = 0; b < K2; b++)
            for (int c = 0; c < K3; c++) {
                std::complex<double> s(0.0, 0.0);
                for (int i = 0; i < K1; i++)
                    for (int k = 0; k < K2; k++)
                        for (int n = 0; n < K3; n++)
                            if (cg[i][k][n] != 0.0)
                                s += Q1[i][a] * Q2[k][b] * std::conj(Q3[n][c]) * cg[i][k][n];
                double r = s.real();
                tmp[(a*K2 + b)*K3 + c] = r;
                nrm += r * r;
            }
    nrm = std::sqrt(nrm);
    for (int e = 0; e < K1*K2*K3; e++) outv[e] = (float)(tmp[e] / nrm);
}

static void build_consts(Consts& cc)
{
    const int npaths[3] = {3, 4, 4};
    for (int p = 0; p < 11; p++) {
        real_w3j(T_L1[p], T_L2[p], T_L3[p], cc.C + T_CO[p]);
        int l3 = T_L3[p];
        cc.scale[p] = (float)std::sqrt((2.0*l3 + 1.0) / (npaths[l3] * 256.0));
    }
    cc.dotmul = (float)(std::sqrt(1.0 / 768.0) / 12.0);
}

// ============================================================================
// Launch
// ============================================================================
extern "C" void kernel_launch(void* const* d_in, const int* in_sizes, int n_in,
                              void* d_out, int out_size)
{
    const float* x    = (const float*)d_in[0];
    const float* wq   = (const float*)d_in[4];
    const float* wk   = (const float*)d_in[5];
    const float* wv   = (const float*)d_in[6];
    const float* wdot = (const float*)d_in[7];
    float* out = (float*)d_out;

    const int N = in_sizes[0] / 144;

    Consts cc;
    build_consts(cc);   // deterministic, recomputed every call

    cudaFuncSetAttribute(tfn_kernel, cudaFuncAttributeMaxDynamicSharedMemorySize, SMEM_BYTES);

    const int grid = (N + 15) / 16;
    tfn_kernel<<<grid, 256, SMEM_BYTES>>>(x, wq, wk, wv, wdot, out, N, cc);
}

// round 12
// speedup vs baseline: 1.0137x; 1.0137x over previous
#include <cuda_runtime.h>
#include <cuda_bf16.h>
#include <math.h>
#include <complex>
#include <algorithm>
#include <stdint.h>

// ============================================================================
// Problem constants
// ============================================================================
// irreps: 16 x (0e + 1o + 2e), FEAT = 144
// PATHS (l1,l2,l3) x 11, weights w_* : [11,16,16,16], w_dot : [3,16,16]

constexpr int T_L1[11] = {0,1,2,0,1,1,2,0,1,2,2};
constexpr int T_L2[11] = {0,1,2,1,0,2,1,2,1,0,2};
constexpr int T_L3[11] = {0,0,0,1,1,1,1,2,2,2,2};
constexpr int T_CO[11] = {0,1,10,35,44,53,98,143,168,213,238};
constexpr int C_TOTAL  = 363;
constexpr int T_IOFF[3] = {0,16,64};   // float offset of l-block within 144 (compile-time use only)
constexpr int T_KOFF[3] = {0,1,4};     // k offset within 9-wide register acc (compile-time use only)

struct Consts {
    float C[C_TOTAL];   // real Wigner-3j per path, unit Frobenius norm
    float scale[3];     // per-l3: sqrt((2l3+1)/(n_paths[l3]*256))
    float dotmul;       // sqrt(1/768)/12
};

// ============================================================================
// Shared memory layout (float offsets)
// ============================================================================
#define SM_W        0          // wT[t][wo][uv]: t stride 4160, row stride 260
#define W_T_STRIDE  4160
#define W_R_STRIDE  260        // 260 mod 32 == 4 -> exact 2-phase LDS.128
#define SM_C        12480      // 363 (+pad)
#define SM_WD       12848      // 768
#define SM_X        13616      // 16 x 144
#define SM_OUT      15920      // 16 x 3 x 144 (q,k,v final)
#define SM_B        22832      // b planes: [node][k][uv]
#define B_N_STRIDE  1360       // 5*272 ; 1360 mod 32 == 16 (node complement)
#define B_K_STRIDE  272        // 256 + 16 pad
#define SM_TOTAL    44592      // floats
#define SMEM_BYTES  (SM_TOTAL * 4)   // 178368 bytes

// Pre-transposed weights: wT_g[t][P][wo][uv]  (t: 0=q,1=k,2=v)
__device__ float g_wT[3 * 11 * 4096];

// ============================================================================
// f32x2 helpers
// ============================================================================
__device__ __forceinline__ void fma2(unsigned long long& acc,
                                     unsigned long long a, unsigned long long b)
{
    asm("fma.rn.f32x2 %0, %1, %2, %0;" : "+l"(acc) : "l"(a), "l"(b));
}
__device__ __forceinline__ void lds_v2u64(unsigned long long& a,
                                          unsigned long long& b, uint32_t addr)
{
    asm("ld.shared.v2.u64 {%0,%1},[%2];" : "=l"(a), "=l"(b) : "r"(addr));
}
__device__ __forceinline__ float acc_sum(unsigned long long a)
{
    uint32_t lo, hi;
    asm("mov.b64 {%0,%1},%2;" : "=r"(lo), "=r"(hi) : "l"(a));
    return __uint_as_float(lo) + __uint_as_float(hi);
}

// ============================================================================
// Step A+B: build b[uv,k] into k-major planes  (lane = (node, v))
// ============================================================================
template<int P>
__device__ __forceinline__ void build_b(float* __restrict__ sm, int wid, int lane)
{
    constexpr int L1 = T_L1[P], L2 = T_L2[P], L3 = T_L3[P];
    constexpr int K1 = 2*L1+1, K2 = 2*L2+1, K3 = 2*L3+1;
    constexpr int O1 = T_IOFF[L1], O2 = T_IOFF[L2], CO = T_CO[P];

    const int nd = lane >> 4;
    const int v  = lane & 15;
    const int nl = wid*2 + nd;
    const float* xn = sm + SM_X + nl*144;
    float*       bp = sm + SM_B + nl*B_N_STRIDE + v;   // write bp[k*272 + u*16]
    const float* Cs = sm + SM_C + CO;

    float areg[K1*K3];
    {
        float xr[K2];
        #pragma unroll
        for (int j = 0; j < K2; j++) xr[j] = xn[O2 + v*K2 + j];
        #pragma unroll
        for (int i = 0; i < K1; i++)
            #pragma unroll
            for (int k = 0; k < K3; k++) {
                float s = 0.f;
                #pragma unroll
                for (int j = 0; j < K2; j++)
                    s = fmaf(xr[j], Cs[(i*K2 + j)*K3 + k], s);
                areg[i*K3 + k] = s;
            }
    }
    #pragma unroll 4
    for (int u = 0; u < 16; u++) {
        float xr[K1];
        #pragma unroll
        for (int i = 0; i < K1; i++) xr[i] = xn[O1 + u*K1 + i];
        #pragma unroll
        for (int k = 0; k < K3; k++) {
            float s = 0.f;
            #pragma unroll
            for (int i = 0; i < K1; i++)
                s = fmaf(xr[i], areg[i*K3 + k], s);
            bp[k*B_K_STRIDE + u*16] = s;
        }
    }
}

// ============================================================================
// Heavy contraction: acc[t][k] += sum_uv b[uv,k] W_t[uv,wo]   (lane = (node, wo))
// f32x2 pairs over adjacent uv; running accumulator across all paths.
// ============================================================================
template<int P>
__device__ __forceinline__ void run_heavy(uint32_t smb, int h, int wo, int wid,
                                          unsigned long long (&acc)[3][9])
{
    constexpr int L3 = T_L3[P], K3 = 2*L3+1, KO = T_KOFF[L3];
    const uint32_t bb = smb + (uint32_t)(SM_B + (wid*2 + h)*B_N_STRIDE) * 4u;
    const uint32_t wb = smb + (uint32_t)(SM_W + wo*W_R_STRIDE) * 4u;

    #pragma unroll 4
    for (int s = 0; s < 64; s++) {
        unsigned long long b01[K3], b23[K3];
        unsigned long long w01[3], w23[3];
        #pragma unroll
        for (int k = 0; k < K3; k++)
            lds_v2u64(b01[k], b23[k], bb + (uint32_t)(k*(B_K_STRIDE*4)) + (uint32_t)s*16u);
        #pragma unroll
        for (int t = 0; t < 3; t++)
            lds_v2u64(w01[t], w23[t], wb + (uint32_t)(t*(W_T_STRIDE*4)) + (uint32_t)s*16u);
        #pragma unroll
        for (int t = 0; t < 3; t++)
            #pragma unroll
            for (int k = 0; k < K3; k++) {
                fma2(acc[t][KO+k], w01[t], b01[k]);
                fma2(acc[t][KO+k], w23[t], b23[k]);
            }
    }
}

// ============================================================================
// Epilogue dot-product part (half-warp per node, lane = u)
// ============================================================================
template<int L, int CO_, int DP>
__device__ __forceinline__ float dot_part(const float* __restrict__ sm,
                                          const float* __restrict__ qv,
                                          const float* __restrict__ kv, int u)
{
    constexpr int K = 2*L+1, OFF = T_IOFF[L];
    const float* Csm = sm + SM_C + CO_;
    const float* wd  = sm + SM_WD + DP*256 + u*16;
    float qm[K];
    #pragma unroll
    for (int m = 0; m < K; m++) qm[m] = qv[OFF + u*K + m];
    float qc[K];
    #pragma unroll
    for (int m2 = 0; m2 < K; m2++) {
        float s = 0.f;
        #pragma unroll
        for (int m = 0; m < K; m++) s = fmaf(qm[m], Csm[m*K + m2], s);
        qc[m2] = s;
    }
    float acc = 0.f;
    #pragma unroll
    for (int vv = 0; vv < 16; vv++) {
        float t = 0.f;
        #pragma unroll
        for (int m2 = 0; m2 < K; m2++) t = fmaf(qc[m2], kv[OFF + vv*K + m2], t);
        acc = fmaf(t, wd[vv], acc);
    }
    return acc;
}

// ============================================================================
// Pre-kernel: transpose w_{q,k,v}[P][uv][wo] -> g_wT[t][P][wo][uv]
// ============================================================================
__global__ void transpose_w_kernel(const float* __restrict__ wq,
                                   const float* __restrict__ wk,
                                   const float* __restrict__ wv)
{
    int idx = blockIdx.x * blockDim.x + threadIdx.x;
    if (idx >= 3*11*4096) return;
    int t  = idx / 45056;
    int r  = idx - t*45056;
    int P  = r >> 12;
    int e  = r & 4095;
    int wo = e >> 8;
    int uv = e & 255;
    const float* src = (t == 0) ? wq : (t == 1) ? wk : wv;
    g_wT[idx] = src[P*4096 + uv*16 + wo];
}

// ============================================================================
// Main kernel: 256 threads, 16 nodes/CTA
// ============================================================================
__global__ void __launch_bounds__(256, 1)
tfn_kernel(const float* __restrict__ x,
           const float* __restrict__ wdot,
           float* __restrict__ out, int N, Consts cc)
{
    extern __shared__ float sm[];
    const uint32_t smb = (uint32_t)__cvta_generic_to_shared(sm);
    const int tid  = threadIdx.x;
    const int lane = tid & 31;
    const int wid  = tid >> 5;
    const int base = blockIdx.x * 16;
    const int h    = lane & 1;       // heavy-loop node select
    const int wo   = lane >> 1;      // heavy-loop output w

    // ---- stage constants, w_dot, x tile
    for (int i = tid; i < C_TOTAL; i += 256) sm[SM_C + i] = cc.C[i];
    for (int i = tid; i < 768; i += 256)     sm[SM_WD + i] = wdot[i];
    {
        const float4* xg = reinterpret_cast<const float4*>(x);
        float4* xs = reinterpret_cast<float4*>(sm + SM_X);
        const size_t lim = (size_t)N * 36;
        for (int i = tid; i < 576; i += 256) {
            size_t g = (size_t)base * 36 + i;
            xs[i] = (g < lim) ? xg[g] : make_float4(0.f, 0.f, 0.f, 0.f);
        }
    }
    __syncthreads();

    // running f32x2 accumulators for all paths: [tensor][k-total(9)]
    unsigned long long acc[3][9];
    #pragma unroll
    for (int t = 0; t < 3; t++)
        #pragma unroll
        for (int k = 0; k < 9; k++) acc[t][k] = 0ull;

#define DO_PATH(P)                                                                   \
    {                                                                                \
        /* stage wT[t][wo][uv] for this path (coalesced float4 copies) */            \
        const float4* src4 = reinterpret_cast<const float4*>(g_wT);                  \
        for (int i = tid; i < 3072; i += 256) {                                      \
            int t   = i >> 10;                                                       \
            int rem = i & 1023;                                                      \
            int wor = rem >> 6;                                                      \
            int uq  = rem & 63;                                                      \
            float4 val = src4[(t*11 + (P))*1024 + rem];                              \
            *reinterpret_cast<float4*>(sm + SM_W + t*W_T_STRIDE                      \
                                       + wor*W_R_STRIDE + uq*4) = val;               \
        }                                                                            \
        build_b<P>(sm, wid, lane);                                                   \
        __syncthreads();                                                             \
        run_heavy<P>(smb, h, wo, wid, acc);                                          \
        __syncthreads();                                                             \
    }

    DO_PATH(0)  DO_PATH(1)  DO_PATH(2)  DO_PATH(3)  DO_PATH(4)
    DO_PATH(5)  DO_PATH(6)  DO_PATH(7)  DO_PATH(8)  DO_PATH(9)  DO_PATH(10)
#undef DO_PATH

    // ---- flush accumulators to SM_OUT (each lane fully owns (node,wo) outputs)
    // l3 cases written explicitly: (IOFF,KOFF,K3) = (0,0,1), (16,1,3), (64,4,5)
    {
        float* od = sm + SM_OUT + (wid*2 + h)*432;
        const float s0 = cc.scale[0], s1 = cc.scale[1], s2 = cc.scale[2];
        #pragma unroll
        for (int t = 0; t < 3; t++) {
            od[t*144 + wo] = s0 * acc_sum(acc[t][0]);
            #pragma unroll
            for (int k = 0; k < 3; k++)
                od[t*144 + 16 + wo*3 + k] = s1 * acc_sum(acc[t][1 + k]);
            #pragma unroll
            for (int k = 0; k < 5; k++)
                od[t*144 + 64 + wo*5 + k] = s2 * acc_sum(acc[t][4 + k]);
        }
    }
    __syncthreads();

    // ---- epilogue: dot(q,k), attn, elu(attn*v) -> gmem
    {
        const int nd = lane >> 4;
        const int u  = lane & 15;
        const int nl = wid*2 + nd;
        const float* qv = sm + SM_OUT + nl*432;
        const float* kv = qv + 144;
        const float* vv = qv + 288;

        float dacc = dot_part<0, 0, 0>(sm, qv, kv, u)
                   + dot_part<1, 1, 1>(sm, qv, kv, u)
                   + dot_part<2,10, 2>(sm, qv, kv, u);
        dacc += __shfl_xor_sync(0xffffffffu, dacc, 1);
        dacc += __shfl_xor_sync(0xffffffffu, dacc, 2);
        dacc += __shfl_xor_sync(0xffffffffu, dacc, 4);
        dacc += __shfl_xor_sync(0xffffffffu, dacc, 8);

        float e    = expf(dacc * cc.dotmul);
        float attn = e / (e + 1e-10f);

        const int ng = base + nl;
        if (ng < N) {
            float* og = out + (size_t)ng * 144;
            #pragma unroll
            for (int t = u; t < 144; t += 16) {
                float val = attn * vv[t];
                og[t] = (val > 0.f) ? val : expm1f(val);
            }
        }
    }
}

// ============================================================================
// Host: exact e3nn real Wigner-3j construction (same algorithm as reference)
// ============================================================================
static double factd(int n) { double r = 1.0; for (int i = 2; i <= n; i++) r *= i; return r; }

static double su2_cg(int j1, int m1, int j2, int m2, int j3, int m3)
{
    if (m3 != m1 + m2) return 0.0;
    int vmin = std::max(std::max(-j1 + j2 + m3, -j1 + m1), 0);
    int vmax = std::min(std::min(j2 + j3 + m1, j3 - j1 + j2), j3 + m3);
    double C = std::sqrt((2.0*j3 + 1.0) * factd(j3 + j1 - j2) * factd(j3 - j1 + j2)
                         * factd(j1 + j2 - j3) * factd(j3 + m3) * factd(j3 - m3)
                         / (factd(j1 + j2 + j3 + 1) * factd(j1 - m1) * factd(j1 + m1)
                            * factd(j2 - m2) * factd(j2 + m2)));
    double S = 0.0;
    for (int v = vmin; v <= vmax; v++) {
        double sgn = ((v + j2 + m2) & 1) ? -1.0 : 1.0;
        S += sgn * factd(j2 + j3 + m1 - v) * factd(j1 - m1 + v)
             / (factd(v) * factd(j3 - j1 + j2 - v) * factd(j3 + m3 - v)
                * factd(v + j1 - j2 - m3));
    }
    return C * S;
}

static void qmat(int l, std::complex<double> q[5][5])
{
    for (int i = 0; i < 5; i++) for (int j = 0; j < 5; j++) q[i][j] = 0.0;
    const double is2 = 1.0 / std::sqrt(2.0);
    for (int m = -l; m < 0; m++) {
        q[l + m][l - m] = is2;
        q[l + m][l + m] = std::complex<double>(0.0, -is2);
    }
    q[l][l] = 1.0;
    for (int m = 1; m <= l; m++) {
        double sg = (m & 1) ? -1.0 : 1.0;
        q[l + m][l + m] = sg * is2;
        q[l + m][l - m] = std::complex<double>(0.0, sg * is2);
    }
    std::complex<double> ph(1.0, 0.0);
    for (int t = 0; t < l; t++) ph *= std::complex<double>(0.0, -1.0);  // (-1j)^l
    for (int i = 0; i < 2*l + 1; i++)
        for (int j = 0; j < 2*l + 1; j++) q[i][j] *= ph;
}

static void real_w3j(int l1, int l2, int l3, float* outv)
{
    const int K1 = 2*l1 + 1, K2 = 2*l2 + 1, K3 = 2*l3 + 1;
    std::complex<double> Q1[5][5], Q2[5][5], Q3[5][5];
    qmat(l1, Q1); qmat(l2, Q2); qmat(l3, Q3);

    double cg[5][5][5];
    for (int i = 0; i < K1; i++)
        for (int k = 0; k < K2; k++)
            for (int n = 0; n < K3; n++)
                cg[i][k][n] = su2_cg(l1, i - l1, l2, k - l2, l3, n - l3);

    double tmp[125]; double nrm = 0.0;
    for (int a = 0; a < K1; a++)
        for (int b = 0; b < K2; b++)
            for (int c = 0; c < K3; c++) {
                std::complex<double> s(0.0, 0.0);
                for (int i = 0; i < K1; i++)
                    for (int k = 0; k < K2; k++)
                        for (int n = 0; n < K3; n++)
                            if (cg[i][k][n] != 0.0)
                                s += Q1[i][a] * Q2[k][b] * std::conj(Q3[n][c]) * cg[i][k][n];
                double r = s.real();
                tmp[(a*K2 + b)*K3 + c] = r;
                nrm += r * r;
            }
    nrm = std::sqrt(nrm);
    for (int e = 0; e < K1*K2*K3; e++) outv[e] = (float)(tmp[e] / nrm);
}

static void build_consts(Consts& cc)
{
    const int npaths[3] = {3, 4, 4};
    for (int p = 0; p < 11; p++)
        real_w3j(T_L1[p], T_L2[p], T_L3[p], cc.C + T_CO[p]);
    for (int l3 = 0; l3 < 3; l3++)
        cc.scale[l3] = (float)std::sqrt((2.0*l3 + 1.0) / (npaths[l3] * 256.0));
    cc.dotmul = (float)(std::sqrt(1.0 / 768.0) / 12.0);
}

// ============================================================================
// Launch
// ============================================================================
extern "C" void kernel_launch(void* const* d_in, const int* in_sizes, int n_in,
                              void* d_out, int out_size)
{
    const float* x    = (const float*)d_in[0];
    const float* wq   = (const float*)d_in[4];
    const float* wk   = (const float*)d_in[5];
    const float* wv   = (const float*)d_in[6];
    const float* wdot = (const float*)d_in[7];
    float* out = (float*)d_out;

    const int N = in_sizes[0] / 144;

    Consts cc;
    build_consts(cc);   // deterministic, recomputed every call

    transpose_w_kernel<<<(3*11*4096 + 255) / 256, 256>>>(wq, wk, wv);

    cudaFuncSetAttribute(tfn_kernel, cudaFuncAttributeMaxDynamicSharedMemorySize, SMEM_BYTES);
    const int grid = (N + 15) / 16;
    tfn_kernel<<<grid, 256, SMEM_BYTES>>>(x, wdot, out, N, cc);
}

// round 13
// speedup vs baseline: 1.1432x; 1.1278x over previous
#include <cuda_runtime.h>
#include <cuda_bf16.h>
#include <math.h>
#include <complex>
#include <algorithm>
#include <stdint.h>

// ============================================================================
// Problem constants
// ============================================================================
constexpr int T_L1[11] = {0,1,2,0,1,1,2,0,1,2,2};
constexpr int T_L2[11] = {0,1,2,1,0,2,1,2,1,0,2};
constexpr int T_L3[11] = {0,0,0,1,1,1,1,2,2,2,2};
constexpr int T_CO[11] = {0,1,10,35,44,53,98,143,168,213,238};
constexpr int C_TOTAL  = 363;
constexpr int T_IOFF[3] = {0,16,64};   // compile-time use only
constexpr int T_KOFF[3] = {0,1,4};     // compile-time use only

struct Consts {
    float C[C_TOTAL];
    float scale[3];
    float dotmul;
};

// ============================================================================
// Shared memory layout (float offsets)
// ============================================================================
#define SM_W        0          // wT[t][wo][uv]
#define W_T_STRIDE  4160
#define W_R_STRIDE  260        // 260 mod 32 == 4 -> exact 2-phase LDS.128
#define SM_C        12480
#define SM_WD       12848
#define SM_X        13616      // 16 x 144
#define SM_OUT      15920      // plane 0: 16 x 3 x 144
#define SM_OUT2     22832      // plane 1: 16 x 3 x 144
#define SM_B        29744      // b planes: [node][k][uv]
#define B_N_STRIDE  1360
#define B_K_STRIDE  272
#define SM_TOTAL    51504
#define SMEM_BYTES  (SM_TOTAL * 4)   // 206016 bytes

#define THREADS 512

// Pre-transposed weights: g_wT[t][P][wo][uv]
__device__ float g_wT[3 * 11 * 4096];

// ============================================================================
// f32x2 helpers
// ============================================================================
__device__ __forceinline__ void fma2(unsigned long long& acc,
                                     unsigned long long a, unsigned long long b)
{
    asm("fma.rn.f32x2 %0, %1, %2, %0;" : "+l"(acc) : "l"(a), "l"(b));
}
__device__ __forceinline__ void lds_v2u64(unsigned long long& a,
                                          unsigned long long& b, uint32_t addr)
{
    asm("ld.shared.v2.u64 {%0,%1},[%2];" : "=l"(a), "=l"(b) : "r"(addr));
}
__device__ __forceinline__ float acc_sum(unsigned long long a)
{
    uint32_t lo, hi;
    asm("mov.b64 {%0,%1},%2;" : "=r"(lo), "=r"(hi) : "l"(a));
    return __uint_as_float(lo) + __uint_as_float(hi);
}

// ============================================================================
// Step A+B: build b[uv,k] k-major. Warp w builds node w.
// lane = (uh = lane>>4, v = lane&15); each uh-half covers u in [uh*8, uh*8+8)
// ============================================================================
template<int P>
__device__ __forceinline__ void build_b(float* __restrict__ sm, int wid, int lane)
{
    constexpr int L1 = T_L1[P], L2 = T_L2[P], L3 = T_L3[P];
    constexpr int K1 = 2*L1+1, K2 = 2*L2+1, K3 = 2*L3+1;
    constexpr int O1 = T_IOFF[L1], O2 = T_IOFF[L2], CO = T_CO[P];

    const int uh = lane >> 4;
    const int v  = lane & 15;
    const int nl = wid;                 // node slot 0..15
    const float* xn = sm + SM_X + nl*144;
    float*       bp = sm + SM_B + nl*B_N_STRIDE + v;
    const float* Cs = sm + SM_C + CO;

    float areg[K1*K3];
    {
        float xr[K2];
        #pragma unroll
        for (int j = 0; j < K2; j++) xr[j] = xn[O2 + v*K2 + j];
        #pragma unroll
        for (int i = 0; i < K1; i++)
            #pragma unroll
            for (int k = 0; k < K3; k++) {
                float s = 0.f;
                #pragma unroll
                for (int j = 0; j < K2; j++)
                    s = fmaf(xr[j], Cs[(i*K2 + j)*K3 + k], s);
                areg[i*K3 + k] = s;
            }
    }
    const int u0 = uh * 8;
    #pragma unroll 4
    for (int du = 0; du < 8; du++) {
        const int u = u0 + du;
        float xr[K1];
        #pragma unroll
        for (int i = 0; i < K1; i++) xr[i] = xn[O1 + u*K1 + i];
        #pragma unroll
        for (int k = 0; k < K3; k++) {
            float s = 0.f;
            #pragma unroll
            for (int i = 0; i < K1; i++)
                s = fmaf(xr[i], areg[i*K3 + k], s);
            bp[k*B_K_STRIDE + u*16] = s;
        }
    }
}

// ============================================================================
// Heavy contraction over an s-half: acc[t][k] += sum_uv b[uv,k] W_t[uv,wo]
// Warp w: nodes 2*(w&7)+h (h=lane&1), wo=lane>>1, s in [ (w>>3)*32, +32 )
// ============================================================================
template<int P>
__device__ __forceinline__ void run_heavy(uint32_t smb, int h, int wo,
                                          int npair, int s0,
                                          unsigned long long (&acc)[3][9])
{
    constexpr int L3 = T_L3[P], K3 = 2*L3+1, KO = T_KOFF[L3];
    const uint32_t bb = smb + (uint32_t)(SM_B + (npair*2 + h)*B_N_STRIDE) * 4u
                            + (uint32_t)s0*16u;
    const uint32_t wb = smb + (uint32_t)(SM_W + wo*W_R_STRIDE) * 4u
                            + (uint32_t)s0*16u;

    #pragma unroll 2
    for (int s = 0; s < 32; s++) {
        unsigned long long b01[K3], b23[K3];
        unsigned long long w01[3], w23[3];
        #pragma unroll
        for (int k = 0; k < K3; k++)
            lds_v2u64(b01[k], b23[k], bb + (uint32_t)(k*(B_K_STRIDE*4)) + (uint32_t)s*16u);
        #pragma unroll
        for (int t = 0; t < 3; t++)
            lds_v2u64(w01[t], w23[t], wb + (uint32_t)(t*(W_T_STRIDE*4)) + (uint32_t)s*16u);
        #pragma unroll
        for (int t = 0; t < 3; t++)
            #pragma unroll
            for (int k = 0; k < K3; k++) {
                fma2(acc[t][KO+k], w01[t], b01[k]);
                fma2(acc[t][KO+k], w23[t], b23[k]);
            }
    }
}

// ============================================================================
// Epilogue dot-product part (half-warp per node, lane = u)
// ============================================================================
template<int L, int CO_, int DP>
__device__ __forceinline__ float dot_part(const float* __restrict__ sm,
                                          const float* __restrict__ qv,
                                          const float* __restrict__ kv, int u)
{
    constexpr int K = 2*L+1, OFF = T_IOFF[L];
    const float* Csm = sm + SM_C + CO_;
    const float* wd  = sm + SM_WD + DP*256 + u*16;
    float qm[K];
    #pragma unroll
    for (int m = 0; m < K; m++) qm[m] = qv[OFF + u*K + m];
    float qc[K];
    #pragma unroll
    for (int m2 = 0; m2 < K; m2++) {
        float s = 0.f;
        #pragma unroll
        for (int m = 0; m < K; m++) s = fmaf(qm[m], Csm[m*K + m2], s);
        qc[m2] = s;
    }
    float acc = 0.f;
    #pragma unroll
    for (int vv = 0; vv < 16; vv++) {
        float t = 0.f;
        #pragma unroll
        for (int m2 = 0; m2 < K; m2++) t = fmaf(qc[m2], kv[OFF + vv*K + m2], t);
        acc = fmaf(t, wd[vv], acc);
    }
    return acc;
}

// ============================================================================
// Pre-kernel: transpose w_{q,k,v}[P][uv][wo] -> g_wT[t][P][wo][uv]
// ============================================================================
__global__ void transpose_w_kernel(const float* __restrict__ wq,
                                   const float* __restrict__ wk,
                                   const float* __restrict__ wv)
{
    int idx = blockIdx.x * blockDim.x + threadIdx.x;
    if (idx >= 3*11*4096) return;
    int t  = idx / 45056;
    int r  = idx - t*45056;
    int P  = r >> 12;
    int e  = r & 4095;
    int wo = e >> 8;
    int uv = e & 255;
    const float* src = (t == 0) ? wq : (t == 1) ? wk : wv;
    g_wT[idx] = src[P*4096 + uv*16 + wo];
}

// ============================================================================
// Main kernel: 512 threads, 16 nodes/CTA, s-loop split across warp halves
// ============================================================================
__global__ void __launch_bounds__(THREADS, 1)
tfn_kernel(const float* __restrict__ x,
           const float* __restrict__ wdot,
           float* __restrict__ out, int N, Consts cc)
{
    extern __shared__ float sm[];
    const uint32_t smb = (uint32_t)__cvta_generic_to_shared(sm);
    const int tid  = threadIdx.x;
    const int lane = tid & 31;
    const int wid  = tid >> 5;          // 0..15
    const int base = blockIdx.x * 16;
    const int h     = lane & 1;
    const int wo    = lane >> 1;
    const int npair = wid & 7;          // node pair index
    const int sh    = wid >> 3;         // s-half
    const int s0    = sh * 32;

    // ---- stage constants, w_dot, x tile
    for (int i = tid; i < C_TOTAL; i += THREADS) sm[SM_C + i] = cc.C[i];
    for (int i = tid; i < 768; i += THREADS)     sm[SM_WD + i] = wdot[i];
    {
        const float4* xg = reinterpret_cast<const float4*>(x);
        float4* xs = reinterpret_cast<float4*>(sm + SM_X);
        const size_t lim = (size_t)N * 36;
        for (int i = tid; i < 576; i += THREADS) {
            size_t g = (size_t)base * 36 + i;
            xs[i] = (g < lim) ? xg[g] : make_float4(0.f, 0.f, 0.f, 0.f);
        }
    }
    __syncthreads();

    // running f32x2 accumulators: [tensor][k-total(9)]
    unsigned long long acc[3][9];
    #pragma unroll
    for (int t = 0; t < 3; t++)
        #pragma unroll
        for (int k = 0; k < 9; k++) acc[t][k] = 0ull;

#define DO_PATH(P)                                                                   \
    {                                                                                \
        const float4* src4 = reinterpret_cast<const float4*>(g_wT);                  \
        for (int i = tid; i < 3072; i += THREADS) {                                  \
            int t   = i >> 10;                                                       \
            int rem = i & 1023;                                                      \
            int wor = rem >> 6;                                                      \
            int uq  = rem & 63;                                                      \
            float4 val = src4[(t*11 + (P))*1024 + rem];                              \
            *reinterpret_cast<float4*>(sm + SM_W + t*W_T_STRIDE                      \
                                       + wor*W_R_STRIDE + uq*4) = val;               \
        }                                                                            \
        build_b<P>(sm, wid, lane);                                                   \
        __syncthreads();                                                             \
        run_heavy<P>(smb, h, wo, npair, s0, acc);                                    \
        __syncthreads();                                                             \
    }

    DO_PATH(0)  DO_PATH(1)  DO_PATH(2)  DO_PATH(3)  DO_PATH(4)
    DO_PATH(5)  DO_PATH(6)  DO_PATH(7)  DO_PATH(8)  DO_PATH(9)  DO_PATH(10)
#undef DO_PATH

    // ---- flush partial accumulators; plane per s-half (no cross-warp conflicts)
    {
        float* od = sm + (sh ? SM_OUT2 : SM_OUT) + (npair*2 + h)*432;
        const float s0_ = cc.scale[0], s1_ = cc.scale[1], s2_ = cc.scale[2];
        #pragma unroll
        for (int t = 0; t < 3; t++) {
            od[t*144 + wo] = s0_ * acc_sum(acc[t][0]);
            #pragma unroll
            for (int k = 0; k < 3; k++)
                od[t*144 + 16 + wo*3 + k] = s1_ * acc_sum(acc[t][1 + k]);
            #pragma unroll
            for (int k = 0; k < 5; k++)
                od[t*144 + 64 + wo*5 + k] = s2_ * acc_sum(acc[t][4 + k]);
        }
    }
    __syncthreads();

    // ---- sum the two s-half planes into plane 0
    for (int i = tid; i < 6912; i += THREADS)
        sm[SM_OUT + i] += sm[SM_OUT2 + i];
    __syncthreads();

    // ---- epilogue on warps 0..7: dot(q,k), attn, elu(attn*v) -> gmem
    if (wid < 8) {
        const int nd = lane >> 4;
        const int u  = lane & 15;
        const int nl = wid*2 + nd;
        const float* qv = sm + SM_OUT + nl*432;
        const float* kv = qv + 144;
        const float* vv = qv + 288;

        float dacc = dot_part<0, 0, 0>(sm, qv, kv, u)
                   + dot_part<1, 1, 1>(sm, qv, kv, u)
                   + dot_part<2,10, 2>(sm, qv, kv, u);
        dacc += __shfl_xor_sync(0xffffffffu, dacc, 1);
        dacc += __shfl_xor_sync(0xffffffffu, dacc, 2);
        dacc += __shfl_xor_sync(0xffffffffu, dacc, 4);
        dacc += __shfl_xor_sync(0xffffffffu, dacc, 8);

        float e    = expf(dacc * cc.dotmul);
        float attn = e / (e + 1e-10f);

        const int ng = base + nl;
        if (ng < N) {
            float* og = out + (size_t)ng * 144;
            #pragma unroll
            for (int t = u; t < 144; t += 16) {
                float val = attn * vv[t];
                og[t] = (val > 0.f) ? val : expm1f(val);
            }
        }
    }
}

// ============================================================================
// Host: exact e3nn real Wigner-3j construction (same algorithm as reference)
// ============================================================================
static double factd(int n) { double r = 1.0; for (int i = 2; i <= n; i++) r *= i; return r; }

static double su2_cg(int j1, int m1, int j2, int m2, int j3, int m3)
{
    if (m3 != m1 + m2) return 0.0;
    int vmin = std::max(std::max(-j1 + j2 + m3, -j1 + m1), 0);
    int vmax = std::min(std::min(j2 + j3 + m1, j3 - j1 + j2), j3 + m3);
    double C = std::sqrt((2.0*j3 + 1.0) * factd(j3 + j1 - j2) * factd(j3 - j1 + j2)
                         * factd(j1 + j2 - j3) * factd(j3 + m3) * factd(j3 - m3)
                         / (factd(j1 + j2 + j3 + 1) * factd(j1 - m1) * factd(j1 + m1)
                            * factd(j2 - m2) * factd(j2 + m2)));
    double S = 0.0;
    for (int v = vmin; v <= vmax; v++) {
        double sgn = ((v + j2 + m2) & 1) ? -1.0 : 1.0;
        S += sgn * factd(j2 + j3 + m1 - v) * factd(j1 - m1 + v)
             / (factd(v) * factd(j3 - j1 + j2 - v) * factd(j3 + m3 - v)
                * factd(v + j1 - j2 - m3));
    }
    return C * S;
}

static void qmat(int l, std::complex<double> q[5][5])
{
    for (int i = 0; i < 5; i++) for (int j = 0; j < 5; j++) q[i][j] = 0.0;
    const double is2 = 1.0 / std::sqrt(2.0);
    for (int m = -l; m < 0; m++) {
        q[l + m][l - m] = is2;
        q[l + m][l + m] = std::complex<double>(0.0, -is2);
    }
    q[l][l] = 1.0;
    for (int m = 1; m <= l; m++) {
        double sg = (m & 1) ? -1.0 : 1.0;
        q[l + m][l + m] = sg * is2;
        q[l + m][l - m] = std::complex<double>(0.0, sg * is2);
    }
    std::complex<double> ph(1.0, 0.0);
    for (int t = 0; t < l; t++) ph *= std::complex<double>(0.0, -1.0);  // (-1j)^l
    for (int i = 0; i < 2*l + 1; i++)
        for (int j = 0; j < 2*l + 1; j++) q[i][j] *= ph;
}

static void real_w3j(int l1, int l2, int l3, float* outv)
{
    const int K1 = 2*l1 + 1, K2 = 2*l2 + 1, K3 = 2*l3 + 1;
    std::complex<double> Q1[5][5], Q2[5][5], Q3[5][5];
    qmat(l1, Q1); qmat(l2, Q2); qmat(l3, Q3);

    double cg[5][5][5];
    for (int i = 0; i < K1; i++)
        for (int k = 0; k < K2; k++)
            for (int n = 0; n < K3; n++)
                cg[i][k][n] = su2_cg(l1, i - l1, l2, k - l2, l3, n - l3);

    double tmp[125]; double nrm = 0.0;
    for (int a = 0; a < K1; a++)
        for (int b = 0; b < K2; b++)
            for (int c = 0; c < K3; c++) {
                std::complex<double> s(0.0, 0.0);
                for (int i = 0; i < K1; i++)
                    for (int k = 0; k < K2; k++)
                        for (int n = 0; n < K3; n++)
                            if (cg[i][k][n] != 0.0)
                                s += Q1[i][a] * Q2[k][b] * std::conj(Q3[n][c]) * cg[i][k][n];
                double r = s.real();
                tmp[(a*K2 + b)*K3 + c] = r;
                nrm += r * r;
            }
    nrm = std::sqrt(nrm);
    for (int e = 0; e < K1*K2*K3; e++) outv[e] = (float)(tmp[e] / nrm);
}

static void build_consts(Consts& cc)
{
    const int npaths[3] = {3, 4, 4};
    for (int p = 0; p < 11; p++)
        real_w3j(T_L1[p], T_L2[p], T_L3[p], cc.C + T_CO[p]);
    for (int l3 = 0; l3 < 3; l3++)
        cc.scale[l3] = (float)std::sqrt((2.0*l3 + 1.0) / (npaths[l3] * 256.0));
    cc.dotmul = (float)(std::sqrt(1.0 / 768.0) / 12.0);
}

// ============================================================================
// Launch
// ============================================================================
extern "C" void kernel_launch(void* const* d_in, const int* in_sizes, int n_in,
                              void* d_out, int out_size)
{
    const float* x    = (const float*)d_in[0];
    const float* wq   = (const float*)d_in[4];
    const float* wk   = (const float*)d_in[5];
    const float* wv   = (const float*)d_in[6];
    const float* wdot = (const float*)d_in[7];
    float* out = (float*)d_out;

    const int N = in_sizes[0] / 144;

    Consts cc;
    build_consts(cc);   // deterministic, recomputed every call

    transpose_w_kernel<<<(3*11*4096 + 255) / 256, 256>>>(wq, wk, wv);

    cudaFuncSetAttribute(tfn_kernel, cudaFuncAttributeMaxDynamicSharedMemorySize, SMEM_BYTES);
    const int grid = (N + 15) / 16;
    tfn_kernel<<<grid, THREADS, SMEM_BYTES>>>(x, wdot, out, N, cc);
}